// round 15
// baseline (speedup 1.0000x reference)
#include <cuda_runtime.h>
#include <math.h>

#define NN 4096
#define MAXN 256
#define NGRAPH 64

// ---------------- scratch (device globals; no allocation) ----------------
__device__ float g_f[NN * 64];          // per-layer linear features (both heads)
__device__ float g_xbuf[2][NN * 64];    // layer outputs (ping-pong)
__device__ float g_h[NN * 192];         // concat(x1,x2,x3)
__device__ int   g_col[NN * MAXN];      // CSR columns (contiguous per row)
__device__ int   g_cnt[NN];             // row neighbor counts
__device__ float g_s1p[NN * 2];         // attention src scores [row*2+head]
__device__ float g_s2p[NN * 2];         // attention dst scores [row*2+head]

// ---------------- GEMM f = x@Wcat + b, with fused attention scores -------
// BM=32, BN=64, BK=32, 256 threads. W layout [2][in][32], b [2][32]=[64].
__device__ __forceinline__ void gemm_attn(
    const float* __restrict__ x, int in,
    const float* __restrict__ W, const float* __restrict__ b,
    const float* __restrict__ a1w, const float* __restrict__ a1b,
    const float* __restrict__ a2w, const float* __restrict__ a2b,
    int bid)
{
    __shared__ float As[32][33];   // [kk][row]
    __shared__ float Ws[32][64];   // [kk][col]
    int row0 = bid * 32;
    int t  = threadIdx.x;
    int tc = t & 15;               // col group: cols 4tc..4tc+3 (one head)
    int tr = t >> 4;               // row group: rows 2tr, 2tr+1
    int lr = t >> 3;               // load row 0..31
    int lc = t & 7;                // load k-group (float4)
    float acc[2][4] = {{0.f,0.f,0.f,0.f},{0.f,0.f,0.f,0.f}};

    for (int kb = 0; kb < in; kb += 32) {
        float4 xv = *(const float4*)&x[(size_t)(row0 + lr) * in + kb + 4 * lc];
        As[4*lc+0][lr] = xv.x; As[4*lc+1][lr] = xv.y;
        As[4*lc+2][lr] = xv.z; As[4*lc+3][lr] = xv.w;
#pragma unroll
        for (int j = 0; j < 2; j++) {
            int u  = t + j * 256;
            int kk = u >> 4, q = u & 15;
            int kh = q >> 3, h = (4 * q) & 31;
            float4 wv = *(const float4*)&W[((size_t)kh * in + kb + kk) * 32 + h];
            *(float4*)&Ws[kk][4 * q] = wv;
        }
        __syncthreads();
#pragma unroll
        for (int kk = 0; kk < 32; kk++) {
            float a0 = As[kk][2*tr], a1 = As[kk][2*tr+1];
            float4 wv = *(float4*)&Ws[kk][4*tc];
            acc[0][0] = fmaf(a0, wv.x, acc[0][0]);
            acc[0][1] = fmaf(a0, wv.y, acc[0][1]);
            acc[0][2] = fmaf(a0, wv.z, acc[0][2]);
            acc[0][3] = fmaf(a0, wv.w, acc[0][3]);
            acc[1][0] = fmaf(a1, wv.x, acc[1][0]);
            acc[1][1] = fmaf(a1, wv.y, acc[1][1]);
            acc[1][2] = fmaf(a1, wv.z, acc[1][2]);
            acc[1][3] = fmaf(a1, wv.w, acc[1][3]);
        }
        __syncthreads();
    }

    // epilogue: bias, store f (float4), fused attention score partials
    int col = 4 * tc;
    float b0 = b[col], b1 = b[col+1], b2 = b[col+2], b3 = b[col+3];
    float w10 = a1w[col], w11 = a1w[col+1], w12 = a1w[col+2], w13 = a1w[col+3];
    float w20 = a2w[col], w21 = a2w[col+1], w22 = a2w[col+2], w23 = a2w[col+3];
    float p1[2], p2[2];
#pragma unroll
    for (int r = 0; r < 2; r++) {
        float f0 = acc[r][0]+b0, f1 = acc[r][1]+b1, f2 = acc[r][2]+b2, f3 = acc[r][3]+b3;
        int row = row0 + 2*tr + r;
        float4 fv = {f0, f1, f2, f3};
        *(float4*)&g_f[(size_t)row * 64 + col] = fv;
        p1[r] = f0*w10 + f1*w11 + f2*w12 + f3*w13;
        p2[r] = f0*w20 + f1*w21 + f2*w22 + f3*w23;
    }
#pragma unroll
    for (int o = 4; o; o >>= 1) {
        p1[0] += __shfl_down_sync(0xffffffffu, p1[0], o, 8);
        p1[1] += __shfl_down_sync(0xffffffffu, p1[1], o, 8);
        p2[0] += __shfl_down_sync(0xffffffffu, p2[0], o, 8);
        p2[1] += __shfl_down_sync(0xffffffffu, p2[1], o, 8);
    }
    if ((tc & 7) == 0) {
        int k = tc >> 3;   // head
#pragma unroll
        for (int r = 0; r < 2; r++) {
            int row = row0 + 2*tr + r;
            g_s1p[row * 2 + k] = p1[r] + a1b[k];
            g_s2p[row * 2 + k] = p2[r] + a2b[k];
        }
    }
}

// ---------------- CSR build, software-pipelined (MLP=4) ------------------
__device__ __forceinline__ void csr_step(float4 v, int c0, int lane,
                                         int& base, int* __restrict__ mycol) {
    unsigned lm = (1u << lane) - 1u;
    unsigned m0 = __ballot_sync(0xffffffffu, v.x > 0.0f);
    if (v.x > 0.0f) { int p = base + __popc(m0 & lm); if (p < MAXN) mycol[p] = c0; }
    base += __popc(m0);
    unsigned m1 = __ballot_sync(0xffffffffu, v.y > 0.0f);
    if (v.y > 0.0f) { int p = base + __popc(m1 & lm); if (p < MAXN) mycol[p] = c0 + 1; }
    base += __popc(m1);
    unsigned m2 = __ballot_sync(0xffffffffu, v.z > 0.0f);
    if (v.z > 0.0f) { int p = base + __popc(m2 & lm); if (p < MAXN) mycol[p] = c0 + 2; }
    base += __popc(m2);
    unsigned m3 = __ballot_sync(0xffffffffu, v.w > 0.0f);
    if (v.w > 0.0f) { int p = base + __popc(m3 & lm); if (p < MAXN) mycol[p] = c0 + 3; }
    base += __popc(m3);
}

__device__ __forceinline__ void csr_body(const float* __restrict__ adj, int wrow) {
    int lane = threadIdx.x & 31;
    const float4* row = (const float4*)(adj + (size_t)wrow * NN);
    int* mycol = g_col + (size_t)wrow * MAXN;
    int base = 0;
#pragma unroll 1
    for (int mb = 0; mb < 8; mb++) {
        float4 v0 = row[(mb * 4 + 0) * 32 + lane];
        float4 v1 = row[(mb * 4 + 1) * 32 + lane];
        float4 v2 = row[(mb * 4 + 2) * 32 + lane];
        float4 v3 = row[(mb * 4 + 3) * 32 + lane];
        int c0 = mb * 512 + 4 * lane;
        csr_step(v0, c0,       lane, base, mycol);
        csr_step(v1, c0 + 128, lane, base, mycol);
        csr_step(v2, c0 + 256, lane, base, mycol);
        csr_step(v3, c0 + 384, lane, base, mycol);
    }
    if (lane == 0) g_cnt[wrow] = base < MAXN ? base : MAXN;
}

// ---------------- fused: CSR build + layer-1 GEMM (overlap HBM & FMA) ----
__global__ void fused_csr_gemm1(
    const float* __restrict__ x, const float* __restrict__ adj,
    const float* __restrict__ W, const float* __restrict__ b,
    const float* __restrict__ a1w, const float* __restrict__ a1b,
    const float* __restrict__ a2w, const float* __restrict__ a2b)
{
    if (blockIdx.x < 128) {
        gemm_attn(x, 512, W, b, a1w, a1b, a2w, a2b, blockIdx.x);
    } else {
        int wrow = (blockIdx.x - 128) * 8 + (threadIdx.x >> 5);
        csr_body(adj, wrow);
    }
}

// ---------------- GEMM kernel for layers 2/3 -----------------------------
__global__ void gemm_k(int sel,
    const float* __restrict__ W, const float* __restrict__ b,
    const float* __restrict__ a1w, const float* __restrict__ a1b,
    const float* __restrict__ a2w, const float* __restrict__ a2b)
{
    gemm_attn(g_xbuf[sel], 64, W, b, a1w, a1b, a2w, a2b, blockIdx.x);
}

// ---------------- sparse softmax aggregation, 2 warps per row ------------
// Block 256 = 4 row-groups x 64 threads (warp pair). Phase A: 64 threads
// stride neighbors (disjoint), logits staged to smem, pair-combined
// reductions via smem. Phase B: 4 neighbor streams across the pair
// (offsets 0/2/4/6, step 8); lane = (q=lane>>4, fe=lane&15); one LDG.128
// covers a full 256B feature row; head = fe>>3. 8192 warps chip-wide.
__global__ void __launch_bounds__(256) aggregate(int outsel, int hoff) {
    __shared__ float4 pairs[4][MAXN];      // [group][n] = {off, w0, w1, 0}
    __shared__ float  rm[4][2][2];         // max partials [group][warp][head]
    __shared__ float  rs[4][2][2];         // sum partials
    __shared__ float4 racc[4][2][16];      // phase-B partials [group][warp][fe]
    int t    = threadIdx.x;
    int g    = t >> 6;                     // row group 0..3
    int h    = (t >> 5) & 1;               // warp in pair
    int lane = t & 31;
    int t64  = t & 63;
    int i = blockIdx.x * 4 + g;

    int cnt = g_cnt[i];
    float2 s1 = *(const float2*)&g_s1p[i * 2];
    const float2* __restrict__ s2 = (const float2*)g_s2p;
    const int* __restrict__ mycol = g_col + (size_t)i * MAXN;
    float4* __restrict__ pw = pairs[g];

    // pass 1: raw leaky logits -> smem; per-thread max
    float m0 = -1e30f, m1 = -1e30f;
    for (int n = t64; n < cnt; n += 64) {
        int j = mycol[n];
        float2 sv = s2[j];
        float e0 = s1.x + sv.x; e0 = e0 > 0.f ? e0 : 0.01f * e0;
        float e1 = s1.y + sv.y; e1 = e1 > 0.f ? e1 : 0.01f * e1;
        float4 p = {__int_as_float(j << 8), e0, e1, 0.f};
        pw[n] = p;
        m0 = fmaxf(m0, e0); m1 = fmaxf(m1, e1);
    }
#pragma unroll
    for (int o = 16; o; o >>= 1) {
        m0 = fmaxf(m0, __shfl_xor_sync(0xffffffffu, m0, o));
        m1 = fmaxf(m1, __shfl_xor_sync(0xffffffffu, m1, o));
    }
    if (lane == 0) { rm[g][h][0] = m0; rm[g][h][1] = m1; }
    __syncthreads();
    m0 = fmaxf(rm[g][0][0], rm[g][1][0]);
    m1 = fmaxf(rm[g][0][1], rm[g][1][1]);

    // pass 2: exp + sum, rewrite weights in smem; pad to multiple of 8
    float sm0 = 0.f, sm1 = 0.f;
    for (int n = t64; n < cnt; n += 64) {
        float4 p = pw[n];
        float w0 = __expf(p.y - m0);
        float w1 = __expf(p.z - m1);
        sm0 += w0; sm1 += w1;
        p.y = w0; p.z = w1;
        pw[n] = p;
    }
    int cnt8 = (cnt + 7) & ~7;
    if (t64 < cnt8 - cnt) {
        float4 z = {0.f, 0.f, 0.f, 0.f};
        pw[cnt + t64] = z;
    }
#pragma unroll
    for (int o = 16; o; o >>= 1) {
        sm0 += __shfl_xor_sync(0xffffffffu, sm0, o);
        sm1 += __shfl_xor_sync(0xffffffffu, sm1, o);
    }
    if (lane == 0) { rs[g][h][0] = sm0; rs[g][h][1] = sm1; }
    __syncthreads();
    float inv0 = 1.0f / (rs[g][0][0] + rs[g][1][0]);
    float inv1 = 1.0f / (rs[g][0][1] + rs[g][1][1]);

    // phase B: 4 streams (h,q) over the pair; 2 neighbors per lane-iter
    int q  = lane >> 4;                    // stream within warp
    int fe = lane & 15;                    // 16B slot 0..15
    int k  = fe >> 3;                      // head
    const char* __restrict__ fb = (const char*)g_f + fe * 16;
    float4 acc = {0.f, 0.f, 0.f, 0.f};
#pragma unroll 1
    for (int n = 4 * h + 2 * q; n < cnt8; n += 8) {
        float4 pA = pw[n];
        float4 pB = pw[n + 1];
        float4 fA = *(const float4*)(fb + __float_as_int(pA.x));
        float4 fB = *(const float4*)(fb + __float_as_int(pB.x));
        float wA = k ? pA.z : pA.y;
        float wB = k ? pB.z : pB.y;
        acc.x = fmaf(wA, fA.x, acc.x);
        acc.y = fmaf(wA, fA.y, acc.y);
        acc.z = fmaf(wA, fA.z, acc.z);
        acc.w = fmaf(wA, fA.w, acc.w);
        acc.x = fmaf(wB, fB.x, acc.x);
        acc.y = fmaf(wB, fB.y, acc.y);
        acc.z = fmaf(wB, fB.z, acc.z);
        acc.w = fmaf(wB, fB.w, acc.w);
    }
    acc.x += __shfl_xor_sync(0xffffffffu, acc.x, 16);
    acc.y += __shfl_xor_sync(0xffffffffu, acc.y, 16);
    acc.z += __shfl_xor_sync(0xffffffffu, acc.z, 16);
    acc.w += __shfl_xor_sync(0xffffffffu, acc.w, 16);
    if (q == 0) racc[g][h][fe] = acc;
    __syncthreads();
    if (h == 0 && q == 0) {
        float4 a = racc[g][0][fe];
        float4 b = racc[g][1][fe];
        float inv = k ? inv1 : inv0;
        float4 o4;
        o4.x = fmaxf((a.x + b.x) * inv, 0.f);
        o4.y = fmaxf((a.y + b.y) * inv, 0.f);
        o4.z = fmaxf((a.z + b.z) * inv, 0.f);
        o4.w = fmaxf((a.w + b.w) * inv, 0.f);
        *(float4*)&g_xbuf[outsel][(size_t)i * 64 + fe * 4] = o4;
        *(float4*)&g_h[(size_t)i * 192 + hoff + fe * 4] = o4;
    }
}

// ---------------- fused segment-mean pool + classifier head --------------
__global__ void pool_head(const int* __restrict__ batch,
                          const float* __restrict__ Wf, const float* __restrict__ bf,
                          float* __restrict__ out) {
    int g = blockIdx.x;   // 64
    int t = threadIdx.x;  // 192
    __shared__ float pooled[192];
    __shared__ int sst, sen;
    if (t == 0) {
        int lo = 0, hi = NN;
        while (lo < hi) { int mid = (lo + hi) >> 1; if (batch[mid] < g) lo = mid + 1; else hi = mid; }
        sst = lo;
        hi = NN;
        while (lo < hi) { int mid = (lo + hi) >> 1; if (batch[mid] < g + 1) lo = mid + 1; else hi = mid; }
        sen = lo;
    }
    __syncthreads();
    float s = 0.f;
    for (int r = sst; r < sen; r++) s += g_h[(size_t)r * 192 + t];
    float c = (float)(sen - sst);
    pooled[t] = s / fmaxf(c, 1.0f);
    __syncthreads();
    if (t < 32) {
        float logit = 0.f, v = -1e30f;
        if (t < 10) {
            float acc = bf[t];
            for (int c2 = 0; c2 < 192; c2++) acc = fmaf(pooled[c2], Wf[c2 * 10 + t], acc);
            logit = acc; v = acc;
        }
#pragma unroll
        for (int o = 16; o; o >>= 1) v = fmaxf(v, __shfl_xor_sync(0xffffffffu, v, o));
        float e = (t < 10) ? __expf(logit - v) : 0.f;
        float sm = e;
#pragma unroll
        for (int o = 16; o; o >>= 1) sm += __shfl_xor_sync(0xffffffffu, sm, o);
        if (t < 10) out[g * 10 + t] = e / sm;
    }
}

// ---------------- launch --------------------------------------------------
extern "C" void kernel_launch(void* const* d_in, const int* in_sizes, int n_in,
                              void* d_out, int out_size) {
    const float* x     = (const float*)d_in[0];
    const float* adj   = (const float*)d_in[1];
    const int*   batch = (const int*)d_in[2];
    const float* W[3]   = {(const float*)d_in[3],  (const float*)d_in[9],  (const float*)d_in[15]};
    const float* b[3]   = {(const float*)d_in[4],  (const float*)d_in[10], (const float*)d_in[16]};
    const float* a1w[3] = {(const float*)d_in[5],  (const float*)d_in[11], (const float*)d_in[17]};
    const float* a1b[3] = {(const float*)d_in[6],  (const float*)d_in[12], (const float*)d_in[18]};
    const float* a2w[3] = {(const float*)d_in[7],  (const float*)d_in[13], (const float*)d_in[19]};
    const float* a2b[3] = {(const float*)d_in[8],  (const float*)d_in[14], (const float*)d_in[20]};
    const float* Wf = (const float*)d_in[21];
    const float* bf = (const float*)d_in[22];
    float* out = (float*)d_out;

    // layer 1 GEMM (blocks 0-127) overlapped with CSR build (blocks 128-639)
    fused_csr_gemm1<<<640, 256>>>(x, adj, W[0], b[0], a1w[0], a1b[0], a2w[0], a2b[0]);
    aggregate<<<NN / 4, 256>>>(0, 0);

    gemm_k<<<128, 256>>>(0, W[1], b[1], a1w[1], a1b[1], a2w[1], a2b[1]);
    aggregate<<<NN / 4, 256>>>(1, 64);

    gemm_k<<<128, 256>>>(1, W[2], b[2], a1w[2], a1b[2], a2w[2], a2b[2]);
    aggregate<<<NN / 4, 256>>>(0, 128);

    pool_head<<<NGRAPH, 192>>>(batch, Wf, bf, out);
}

// round 17
// speedup vs baseline: 1.0461x; 1.0461x over previous
#include <cuda_runtime.h>
#include <math.h>

#define NN 4096
#define MAXN 256
#define NGRAPH 64

// ---------------- scratch (device globals; no allocation) ----------------
__device__ float g_f[NN * 64];          // per-layer linear features (both heads)
__device__ float g_xbuf[2][NN * 64];    // layer outputs (ping-pong)
__device__ float g_h[NN * 192];         // concat(x1,x2,x3)
__device__ int   g_col[NN * MAXN];      // CSR columns (contiguous per row)
__device__ int   g_cnt[NN];             // row neighbor counts
__device__ float g_s1p[NN * 2];         // attention src scores [row*2+head]
__device__ float g_s2p[NN * 2];         // attention dst scores [row*2+head]

// ---------------- GEMM f = x@Wcat + b, with fused attention scores -------
// BM=32, BN=64, BK=32, 256 threads. W layout [2][in][32], b [2][32]=[64].
__device__ __forceinline__ void gemm_attn(
    const float* __restrict__ x, int in,
    const float* __restrict__ W, const float* __restrict__ b,
    const float* __restrict__ a1w, const float* __restrict__ a1b,
    const float* __restrict__ a2w, const float* __restrict__ a2b,
    int bid)
{
    __shared__ float As[32][33];   // [kk][row]
    __shared__ float Ws[32][64];   // [kk][col]
    int row0 = bid * 32;
    int t  = threadIdx.x;
    int tc = t & 15;               // col group: cols 4tc..4tc+3 (one head)
    int tr = t >> 4;               // row group: rows 2tr, 2tr+1
    int lr = t >> 3;               // load row 0..31
    int lc = t & 7;                // load k-group (float4)
    float acc[2][4] = {{0.f,0.f,0.f,0.f},{0.f,0.f,0.f,0.f}};

    for (int kb = 0; kb < in; kb += 32) {
        float4 xv = *(const float4*)&x[(size_t)(row0 + lr) * in + kb + 4 * lc];
        As[4*lc+0][lr] = xv.x; As[4*lc+1][lr] = xv.y;
        As[4*lc+2][lr] = xv.z; As[4*lc+3][lr] = xv.w;
#pragma unroll
        for (int j = 0; j < 2; j++) {
            int u  = t + j * 256;
            int kk = u >> 4, q = u & 15;
            int kh = q >> 3, h = (4 * q) & 31;
            float4 wv = *(const float4*)&W[((size_t)kh * in + kb + kk) * 32 + h];
            *(float4*)&Ws[kk][4 * q] = wv;
        }
        __syncthreads();
#pragma unroll
        for (int kk = 0; kk < 32; kk++) {
            float a0 = As[kk][2*tr], a1 = As[kk][2*tr+1];
            float4 wv = *(float4*)&Ws[kk][4*tc];
            acc[0][0] = fmaf(a0, wv.x, acc[0][0]);
            acc[0][1] = fmaf(a0, wv.y, acc[0][1]);
            acc[0][2] = fmaf(a0, wv.z, acc[0][2]);
            acc[0][3] = fmaf(a0, wv.w, acc[0][3]);
            acc[1][0] = fmaf(a1, wv.x, acc[1][0]);
            acc[1][1] = fmaf(a1, wv.y, acc[1][1]);
            acc[1][2] = fmaf(a1, wv.z, acc[1][2]);
            acc[1][3] = fmaf(a1, wv.w, acc[1][3]);
        }
        __syncthreads();
    }

    // epilogue: bias, store f (float4), fused attention score partials
    int col = 4 * tc;
    float b0 = b[col], b1 = b[col+1], b2 = b[col+2], b3 = b[col+3];
    float w10 = a1w[col], w11 = a1w[col+1], w12 = a1w[col+2], w13 = a1w[col+3];
    float w20 = a2w[col], w21 = a2w[col+1], w22 = a2w[col+2], w23 = a2w[col+3];
    float p1[2], p2[2];
#pragma unroll
    for (int r = 0; r < 2; r++) {
        float f0 = acc[r][0]+b0, f1 = acc[r][1]+b1, f2 = acc[r][2]+b2, f3 = acc[r][3]+b3;
        int row = row0 + 2*tr + r;
        float4 fv = {f0, f1, f2, f3};
        *(float4*)&g_f[(size_t)row * 64 + col] = fv;
        p1[r] = f0*w10 + f1*w11 + f2*w12 + f3*w13;
        p2[r] = f0*w20 + f1*w21 + f2*w22 + f3*w23;
    }
#pragma unroll
    for (int o = 4; o; o >>= 1) {
        p1[0] += __shfl_down_sync(0xffffffffu, p1[0], o, 8);
        p1[1] += __shfl_down_sync(0xffffffffu, p1[1], o, 8);
        p2[0] += __shfl_down_sync(0xffffffffu, p2[0], o, 8);
        p2[1] += __shfl_down_sync(0xffffffffu, p2[1], o, 8);
    }
    if ((tc & 7) == 0) {
        int k = tc >> 3;   // head
#pragma unroll
        for (int r = 0; r < 2; r++) {
            int row = row0 + 2*tr + r;
            g_s1p[row * 2 + k] = p1[r] + a1b[k];
            g_s2p[row * 2 + k] = p2[r] + a2b[k];
        }
    }
}

// ---------------- CSR build, software-pipelined (MLP=8) ------------------
__device__ __forceinline__ void csr_step(float4 v, int c0, int lane,
                                         int& base, int* __restrict__ mycol) {
    unsigned lm = (1u << lane) - 1u;
    unsigned m0 = __ballot_sync(0xffffffffu, v.x > 0.0f);
    if (v.x > 0.0f) { int p = base + __popc(m0 & lm); if (p < MAXN) mycol[p] = c0; }
    base += __popc(m0);
    unsigned m1 = __ballot_sync(0xffffffffu, v.y > 0.0f);
    if (v.y > 0.0f) { int p = base + __popc(m1 & lm); if (p < MAXN) mycol[p] = c0 + 1; }
    base += __popc(m1);
    unsigned m2 = __ballot_sync(0xffffffffu, v.z > 0.0f);
    if (v.z > 0.0f) { int p = base + __popc(m2 & lm); if (p < MAXN) mycol[p] = c0 + 2; }
    base += __popc(m2);
    unsigned m3 = __ballot_sync(0xffffffffu, v.w > 0.0f);
    if (v.w > 0.0f) { int p = base + __popc(m3 & lm); if (p < MAXN) mycol[p] = c0 + 3; }
    base += __popc(m3);
}

__device__ __forceinline__ void csr_body(const float* __restrict__ adj, int wrow) {
    int lane = threadIdx.x & 31;
    const float4* row = (const float4*)(adj + (size_t)wrow * NN);
    int* mycol = g_col + (size_t)wrow * MAXN;
    int base = 0;
#pragma unroll 1
    for (int mb = 0; mb < 4; mb++) {
        float4 v0 = row[(mb * 8 + 0) * 32 + lane];
        float4 v1 = row[(mb * 8 + 1) * 32 + lane];
        float4 v2 = row[(mb * 8 + 2) * 32 + lane];
        float4 v3 = row[(mb * 8 + 3) * 32 + lane];
        float4 v4 = row[(mb * 8 + 4) * 32 + lane];
        float4 v5 = row[(mb * 8 + 5) * 32 + lane];
        float4 v6 = row[(mb * 8 + 6) * 32 + lane];
        float4 v7 = row[(mb * 8 + 7) * 32 + lane];
        int c0 = mb * 1024 + 4 * lane;
        csr_step(v0, c0,       lane, base, mycol);
        csr_step(v1, c0 + 128, lane, base, mycol);
        csr_step(v2, c0 + 256, lane, base, mycol);
        csr_step(v3, c0 + 384, lane, base, mycol);
        csr_step(v4, c0 + 512, lane, base, mycol);
        csr_step(v5, c0 + 640, lane, base, mycol);
        csr_step(v6, c0 + 768, lane, base, mycol);
        csr_step(v7, c0 + 896, lane, base, mycol);
    }
    if (lane == 0) g_cnt[wrow] = base < MAXN ? base : MAXN;
}

// ---------------- fused: CSR build + layer-1 GEMM (overlap HBM & FMA) ----
__global__ void fused_csr_gemm1(
    const float* __restrict__ x, const float* __restrict__ adj,
    const float* __restrict__ W, const float* __restrict__ b,
    const float* __restrict__ a1w, const float* __restrict__ a1b,
    const float* __restrict__ a2w, const float* __restrict__ a2b)
{
    if (blockIdx.x < 128) {
        gemm_attn(x, 512, W, b, a1w, a1b, a2w, a2b, blockIdx.x);
    } else {
        int wrow = (blockIdx.x - 128) * 8 + (threadIdx.x >> 5);
        csr_body(adj, wrow);
    }
}

// ---------------- GEMM kernel for layers 2/3 -----------------------------
__global__ void gemm_k(int sel,
    const float* __restrict__ W, const float* __restrict__ b,
    const float* __restrict__ a1w, const float* __restrict__ a1b,
    const float* __restrict__ a2w, const float* __restrict__ a2b)
{
    gemm_attn(g_xbuf[sel], 64, W, b, a1w, a1b, a2w, a2b, blockIdx.x);
}

// ---------------- sparse softmax aggregation, 2 warps per row ------------
// Block 256 = 4 row-groups x 64 threads (warp pair). Phase A: 64 threads
// stride neighbors (disjoint), logits staged to smem, pair-combined
// reductions via smem. Phase B: 4 neighbor streams across the pair
// (offsets 0/2/4/6, step 8); lane = (q=lane>>4, fe=lane&15); one LDG.128
// covers a full 256B feature row; head = fe>>3. 8192 warps chip-wide.
__global__ void __launch_bounds__(256) aggregate(int outsel, int hoff) {
    __shared__ float4 pairs[4][MAXN];      // [group][n] = {off, w0, w1, 0}
    __shared__ float  rm[4][2][2];         // max partials [group][warp][head]
    __shared__ float  rs[4][2][2];         // sum partials
    __shared__ float4 racc[4][2][16];      // phase-B partials [group][warp][fe]
    int t    = threadIdx.x;
    int g    = t >> 6;                     // row group 0..3
    int h    = (t >> 5) & 1;               // warp in pair
    int lane = t & 31;
    int t64  = t & 63;
    int i = blockIdx.x * 4 + g;

    int cnt = g_cnt[i];
    float2 s1 = *(const float2*)&g_s1p[i * 2];
    const float2* __restrict__ s2 = (const float2*)g_s2p;
    const int* __restrict__ mycol = g_col + (size_t)i * MAXN;
    float4* __restrict__ pw = pairs[g];

    // pass 1: raw leaky logits -> smem; per-thread max
    float m0 = -1e30f, m1 = -1e30f;
    for (int n = t64; n < cnt; n += 64) {
        int j = mycol[n];
        float2 sv = s2[j];
        float e0 = s1.x + sv.x; e0 = e0 > 0.f ? e0 : 0.01f * e0;
        float e1 = s1.y + sv.y; e1 = e1 > 0.f ? e1 : 0.01f * e1;
        float4 p = {__int_as_float(j << 8), e0, e1, 0.f};
        pw[n] = p;
        m0 = fmaxf(m0, e0); m1 = fmaxf(m1, e1);
    }
#pragma unroll
    for (int o = 16; o; o >>= 1) {
        m0 = fmaxf(m0, __shfl_xor_sync(0xffffffffu, m0, o));
        m1 = fmaxf(m1, __shfl_xor_sync(0xffffffffu, m1, o));
    }
    if (lane == 0) { rm[g][h][0] = m0; rm[g][h][1] = m1; }
    __syncthreads();
    m0 = fmaxf(rm[g][0][0], rm[g][1][0]);
    m1 = fmaxf(rm[g][0][1], rm[g][1][1]);

    // pass 2: exp + sum, rewrite weights in smem; pad to multiple of 8
    float sm0 = 0.f, sm1 = 0.f;
    for (int n = t64; n < cnt; n += 64) {
        float4 p = pw[n];
        float w0 = __expf(p.y - m0);
        float w1 = __expf(p.z - m1);
        sm0 += w0; sm1 += w1;
        p.y = w0; p.z = w1;
        pw[n] = p;
    }
    int cnt8 = (cnt + 7) & ~7;
    if (t64 < cnt8 - cnt) {
        float4 z = {0.f, 0.f, 0.f, 0.f};
        pw[cnt + t64] = z;
    }
#pragma unroll
    for (int o = 16; o; o >>= 1) {
        sm0 += __shfl_xor_sync(0xffffffffu, sm0, o);
        sm1 += __shfl_xor_sync(0xffffffffu, sm1, o);
    }
    if (lane == 0) { rs[g][h][0] = sm0; rs[g][h][1] = sm1; }
    __syncthreads();
    float inv0 = 1.0f / (rs[g][0][0] + rs[g][1][0]);
    float inv1 = 1.0f / (rs[g][0][1] + rs[g][1][1]);

    // phase B: 4 streams (h,q) over the pair; 2 neighbors per lane-iter
    int q  = lane >> 4;                    // stream within warp
    int fe = lane & 15;                    // 16B slot 0..15
    int k  = fe >> 3;                      // head
    const char* __restrict__ fb = (const char*)g_f + fe * 16;
    float4 acc = {0.f, 0.f, 0.f, 0.f};
#pragma unroll 1
    for (int n = 4 * h + 2 * q; n < cnt8; n += 8) {
        float4 pA = pw[n];
        float4 pB = pw[n + 1];
        float4 fA = *(const float4*)(fb + __float_as_int(pA.x));
        float4 fB = *(const float4*)(fb + __float_as_int(pB.x));
        float wA = k ? pA.z : pA.y;
        float wB = k ? pB.z : pB.y;
        acc.x = fmaf(wA, fA.x, acc.x);
        acc.y = fmaf(wA, fA.y, acc.y);
        acc.z = fmaf(wA, fA.z, acc.z);
        acc.w = fmaf(wA, fA.w, acc.w);
        acc.x = fmaf(wB, fB.x, acc.x);
        acc.y = fmaf(wB, fB.y, acc.y);
        acc.z = fmaf(wB, fB.z, acc.z);
        acc.w = fmaf(wB, fB.w, acc.w);
    }
    acc.x += __shfl_xor_sync(0xffffffffu, acc.x, 16);
    acc.y += __shfl_xor_sync(0xffffffffu, acc.y, 16);
    acc.z += __shfl_xor_sync(0xffffffffu, acc.z, 16);
    acc.w += __shfl_xor_sync(0xffffffffu, acc.w, 16);
    if (q == 0) racc[g][h][fe] = acc;
    __syncthreads();
    if (h == 0 && q == 0) {
        float4 a = racc[g][0][fe];
        float4 b = racc[g][1][fe];
        float inv = k ? inv1 : inv0;
        float4 o4;
        o4.x = fmaxf((a.x + b.x) * inv, 0.f);
        o4.y = fmaxf((a.y + b.y) * inv, 0.f);
        o4.z = fmaxf((a.z + b.z) * inv, 0.f);
        o4.w = fmaxf((a.w + b.w) * inv, 0.f);
        *(float4*)&g_xbuf[outsel][(size_t)i * 64 + fe * 4] = o4;
        *(float4*)&g_h[(size_t)i * 192 + hoff + fe * 4] = o4;
    }
}

// ---------------- fused segment-mean pool + classifier head --------------
__global__ void pool_head(const int* __restrict__ batch,
                          const float* __restrict__ Wf, const float* __restrict__ bf,
                          float* __restrict__ out) {
    int g = blockIdx.x;   // 64
    int t = threadIdx.x;  // 192
    __shared__ float pooled[192];
    __shared__ int sst, sen;
    if (t == 0) {
        int lo = 0, hi = NN;
        while (lo < hi) { int mid = (lo + hi) >> 1; if (batch[mid] < g) lo = mid + 1; else hi = mid; }
        sst = lo;
        hi = NN;
        while (lo < hi) { int mid = (lo + hi) >> 1; if (batch[mid] < g + 1) lo = mid + 1; else hi = mid; }
        sen = lo;
    }
    __syncthreads();
    float s = 0.f;
    for (int r = sst; r < sen; r++) s += g_h[(size_t)r * 192 + t];
    float c = (float)(sen - sst);
    pooled[t] = s / fmaxf(c, 1.0f);
    __syncthreads();
    if (t < 32) {
        float logit = 0.f, v = -1e30f;
        if (t < 10) {
            float acc = bf[t];
            for (int c2 = 0; c2 < 192; c2++) acc = fmaf(pooled[c2], Wf[c2 * 10 + t], acc);
            logit = acc; v = acc;
        }
#pragma unroll
        for (int o = 16; o; o >>= 1) v = fmaxf(v, __shfl_xor_sync(0xffffffffu, v, o));
        float e = (t < 10) ? __expf(logit - v) : 0.f;
        float sm = e;
#pragma unroll
        for (int o = 16; o; o >>= 1) sm += __shfl_xor_sync(0xffffffffu, sm, o);
        if (t < 10) out[g * 10 + t] = e / sm;
    }
}

// ---------------- launch --------------------------------------------------
extern "C" void kernel_launch(void* const* d_in, const int* in_sizes, int n_in,
                              void* d_out, int out_size) {
    const float* x     = (const float*)d_in[0];
    const float* adj   = (const float*)d_in[1];
    const int*   batch = (const int*)d_in[2];
    const float* W[3]   = {(const float*)d_in[3],  (const float*)d_in[9],  (const float*)d_in[15]};
    const float* b[3]   = {(const float*)d_in[4],  (const float*)d_in[10], (const float*)d_in[16]};
    const float* a1w[3] = {(const float*)d_in[5],  (const float*)d_in[11], (const float*)d_in[17]};
    const float* a1b[3] = {(const float*)d_in[6],  (const float*)d_in[12], (const float*)d_in[18]};
    const float* a2w[3] = {(const float*)d_in[7],  (const float*)d_in[13], (const float*)d_in[19]};
    const float* a2b[3] = {(const float*)d_in[8],  (const float*)d_in[14], (const float*)d_in[20]};
    const float* Wf = (const float*)d_in[21];
    const float* bf = (const float*)d_in[22];
    float* out = (float*)d_out;

    // layer 1 GEMM (blocks 0-127) overlapped with CSR build (blocks 128-639)
    fused_csr_gemm1<<<640, 256>>>(x, adj, W[0], b[0], a1w[0], a1b[0], a2w[0], a2b[0]);
    aggregate<<<NN / 4, 256>>>(0, 0);

    gemm_k<<<128, 256>>>(0, W[1], b[1], a1w[1], a1b[1], a2w[1], a2b[1]);
    aggregate<<<NN / 4, 256>>>(1, 64);

    gemm_k<<<128, 256>>>(1, W[2], b[2], a1w[2], a1b[2], a2w[2], a2b[2]);
    aggregate<<<NN / 4, 256>>>(0, 128);

    pool_head<<<NGRAPH, 192>>>(batch, Wf, bf, out);
}